// round 15
// baseline (speedup 1.0000x reference)
#include <cuda_runtime.h>
#include <cuda_bf16.h>

// Zero-initialized device scratch. The last block resets these after use,
// so every graph replay sees a clean state (no init kernel needed).
__device__ unsigned int g_hist[64];
__device__ unsigned int g_done = 0;

// ---------------------------------------------------------------------------
// CONVERGED KERNEL (wall 73.76-73.86us, reproduced 6x: R4/R10-R14).
//
// Fast path: T == 4, step divisible by 4. Fused passthrough copy + collector
// histogram + in-kernel finalize (last-block pattern). Coalesced float4
// grid-stride over the spatial index reading the 4 time streams per
// iteration; single full wave (5 CTAs/SM x 148 SMs = 740 blocks, 48 regs,
// occ 60%).
//
// Roofline argument (validated over 8 mainloop variants):
//   mandatory traffic = 205MB read + 205MB harness-validated write = 410MB;
//   sustained mixed-r/w HBM rate on this part = ~5.7-5.8TB/s (DRAM-bound,
//   not LTS: LTS cap ~6300B/cyc >> observed). Floor = 410MB/5.75TB/s
//   ~= 71.5us kernel + ~2us overhead = ~73.8us wall. This config hits that
//   floor with the lowest register pressure and simplest SASS.
// ---------------------------------------------------------------------------
__global__ void __launch_bounds__(256, 5)
sparsity_fused_t4_v4(const float4* __restrict__ in,
                     float4* __restrict__ out,
                     long long step4,
                     long long n, long long step) {
    unsigned int h0 = 0, h1 = 0, h2 = 0, h3 = 0, h4 = 0;
    const long long stride = (long long)gridDim.x * blockDim.x;
    for (long long j = (long long)blockIdx.x * blockDim.x + threadIdx.x;
         j < step4; j += stride) {
        float4 v0 = in[j];
        float4 v1 = in[step4 + j];
        float4 v2 = in[2 * step4 + j];
        float4 v3 = in[3 * step4 + j];
        out[j]             = v0;
        out[step4 + j]     = v1;
        out[2 * step4 + j] = v2;
        out[3 * step4 + j] = v3;

        float cx = v0.x + v1.x + v2.x + v3.x;
        float cy = v0.y + v1.y + v2.y + v3.y;
        float cz = v0.z + v1.z + v2.z + v3.z;
        float cw = v0.w + v1.w + v2.w + v3.w;
        // collector values are exact small integers 0..4 in fp32
        int bx = (int)cx, by = (int)cy, bz = (int)cz, bw = (int)cw;
        h0 += (bx == 0) + (by == 0) + (bz == 0) + (bw == 0);
        h1 += (bx == 1) + (by == 1) + (bz == 1) + (bw == 1);
        h2 += (bx == 2) + (by == 2) + (bz == 2) + (bw == 2);
        h3 += (bx == 3) + (by == 3) + (bz == 3) + (bw == 3);
        h4 += (bx == 4) + (by == 4) + (bz == 4) + (bw == 4);
    }

    __shared__ unsigned int sh[5];
    if (threadIdx.x < 5) sh[threadIdx.x] = 0u;
    __syncthreads();
    // warp-reduce first to cut shared-atomic traffic 32x
    for (int off = 16; off > 0; off >>= 1) {
        h0 += __shfl_down_sync(0xFFFFFFFFu, h0, off);
        h1 += __shfl_down_sync(0xFFFFFFFFu, h1, off);
        h2 += __shfl_down_sync(0xFFFFFFFFu, h2, off);
        h3 += __shfl_down_sync(0xFFFFFFFFu, h3, off);
        h4 += __shfl_down_sync(0xFFFFFFFFu, h4, off);
    }
    if ((threadIdx.x & 31) == 0) {
        atomicAdd(&sh[0], h0);
        atomicAdd(&sh[1], h1);
        atomicAdd(&sh[2], h2);
        atomicAdd(&sh[3], h3);
        atomicAdd(&sh[4], h4);
    }
    __syncthreads();
    if (threadIdx.x < 5) atomicAdd(&g_hist[threadIdx.x], sh[threadIdx.x]);

    // --- last-block finalize ---
    __threadfence();
    __shared__ bool is_last;
    if (threadIdx.x == 0) {
        unsigned int prev = atomicAdd(&g_done, 1u);
        is_last = (prev == gridDim.x - 1);
    }
    __syncthreads();
    if (is_last && threadIdx.x == 0) {
        float* fo = (float*)out;
        unsigned int c0 = g_hist[0], c1 = g_hist[1], c2 = g_hist[2],
                     c3 = g_hist[3], c4 = g_hist[4];
        unsigned long long ones = (unsigned long long)c1
                                + 2ull * c2 + 3ull * c3 + 4ull * c4;
        double zeros = (double)n - (double)ones;
        fo[n]     = (float)(zeros / (double)n);          // sparsity_ratio
        fo[n + 1] = (float)((double)c0 / (double)step);  // coll zero frac
        fo[n + 2] = (float)c0;
        fo[n + 3] = (float)c1;
        fo[n + 4] = (float)c2;
        fo[n + 5] = (float)c3;
        fo[n + 6] = (float)c4;
        // reset scratch for next (graph-replayed) launch
        g_hist[0] = 0u; g_hist[1] = 0u; g_hist[2] = 0u;
        g_hist[3] = 0u; g_hist[4] = 0u;
        g_done = 0u;
    }
}

// ---------------------------------------------------------------------------
// Generic fallback: any T (<= 63), any step. Scalar loads, shared-atomic
// histogram, same last-block finalize.
// ---------------------------------------------------------------------------
__global__ void sparsity_fused_generic(const float* __restrict__ in,
                                       float* __restrict__ out,
                                       long long step, int T, long long n) {
    extern __shared__ unsigned int shh[];
    for (int k = threadIdx.x; k <= T; k += blockDim.x) shh[k] = 0u;
    __syncthreads();

    const long long stride = (long long)gridDim.x * blockDim.x;
    for (long long j = (long long)blockIdx.x * blockDim.x + threadIdx.x;
         j < step; j += stride) {
        float c = 0.f;
        for (int t = 0; t < T; t++) {
            const long long idx = (long long)t * step + j;
            float v = in[idx];
            out[idx] = v;
            c += v;
        }
        atomicAdd(&shh[(int)c], 1u);
    }
    __syncthreads();
    for (int k = threadIdx.x; k <= T; k += blockDim.x)
        atomicAdd(&g_hist[k], shh[k]);

    __threadfence();
    __shared__ bool is_last;
    if (threadIdx.x == 0) {
        unsigned int prev = atomicAdd(&g_done, 1u);
        is_last = (prev == gridDim.x - 1);
    }
    __syncthreads();
    if (is_last && threadIdx.x == 0) {
        unsigned long long ones = 0ull;
        for (int k = 1; k <= T; k++)
            ones += (unsigned long long)k * (unsigned long long)g_hist[k];
        double zeros = (double)n - (double)ones;
        out[n]     = (float)(zeros / (double)n);
        out[n + 1] = (float)((double)g_hist[0] / (double)step);
        for (int k = 0; k <= T; k++) {
            out[n + 2 + k] = (float)g_hist[k];
            g_hist[k] = 0u;
        }
        g_done = 0u;
    }
}

extern "C" void kernel_launch(void* const* d_in, const int* in_sizes, int n_in,
                              void* d_out, int out_size) {
    const float* spikes = (const float*)d_in[0];
    float* out = (float*)d_out;
    const long long n = (long long)in_sizes[0];

    // out_size = n + 1 + 1 + (T+1)  =>  T = out_size - n - 3
    long long T_ll = (long long)out_size - n - 3;
    int T = (T_ll >= 1 && T_ll <= 63 && (n % T_ll) == 0) ? (int)T_ll : 4;
    const long long step = n / T;

    const int threads = 256;
    if (T == 4 && (step % 4) == 0) {
        const long long step4 = step / 4;
        // Single full wave: 5 CTAs/SM (pinned by __launch_bounds__) x 148 SMs.
        int blocks = 148 * 5;
        long long maxb = (step4 + threads - 1) / threads;
        if ((long long)blocks > maxb) blocks = (int)maxb;
        if (blocks < 1) blocks = 1;
        sparsity_fused_t4_v4<<<blocks, threads>>>(
            (const float4*)spikes, (float4*)out, step4, n, step);
    } else {
        int blocks = 148 * 8;
        long long maxb = (step + threads - 1) / threads;
        if ((long long)blocks > maxb) blocks = (int)maxb;
        if (blocks < 1) blocks = 1;
        sparsity_fused_generic<<<blocks, threads, (T + 1) * sizeof(unsigned int)>>>(
            spikes, out, step, T, n);
    }
}

// round 16
// speedup vs baseline: 1.0039x; 1.0039x over previous
#include <cuda_runtime.h>
#include <cuda_bf16.h>

// Zero-initialized device scratch. The last block resets these after use,
// so every graph replay sees a clean state (no init kernel needed).
__device__ unsigned int g_hist[64];
__device__ unsigned int g_done = 0;

// ---------------------------------------------------------------------------
// CONVERGED KERNEL (wall 73.76-73.86us, reproduced 7x: R4/R10-R15).
//
// Fast path: T == 4, step divisible by 4. Fused passthrough copy + collector
// histogram + in-kernel finalize (last-block pattern). Coalesced float4
// grid-stride over the spatial index reading the 4 time streams per
// iteration; single full wave (5 CTAs/SM x 148 SMs = 740 blocks, 48 regs,
// occ 60%).
//
// Roofline argument (validated over 8 mainloop variants):
//   mandatory traffic = 205MB read + 205MB harness-validated write = 410MB;
//   sustained mixed-r/w HBM rate on this part = ~5.7-5.8TB/s (DRAM-bound,
//   not LTS: LTS cap ~6300B/cyc >> observed). Floor = 410MB/5.75TB/s
//   ~= 71.5us kernel + ~2us overhead = ~73.8us wall. This config hits that
//   floor with the lowest register pressure and simplest SASS.
// ---------------------------------------------------------------------------
__global__ void __launch_bounds__(256, 5)
sparsity_fused_t4_v4(const float4* __restrict__ in,
                     float4* __restrict__ out,
                     long long step4,
                     long long n, long long step) {
    unsigned int h0 = 0, h1 = 0, h2 = 0, h3 = 0, h4 = 0;
    const long long stride = (long long)gridDim.x * blockDim.x;
    for (long long j = (long long)blockIdx.x * blockDim.x + threadIdx.x;
         j < step4; j += stride) {
        float4 v0 = in[j];
        float4 v1 = in[step4 + j];
        float4 v2 = in[2 * step4 + j];
        float4 v3 = in[3 * step4 + j];
        out[j]             = v0;
        out[step4 + j]     = v1;
        out[2 * step4 + j] = v2;
        out[3 * step4 + j] = v3;

        float cx = v0.x + v1.x + v2.x + v3.x;
        float cy = v0.y + v1.y + v2.y + v3.y;
        float cz = v0.z + v1.z + v2.z + v3.z;
        float cw = v0.w + v1.w + v2.w + v3.w;
        // collector values are exact small integers 0..4 in fp32
        int bx = (int)cx, by = (int)cy, bz = (int)cz, bw = (int)cw;
        h0 += (bx == 0) + (by == 0) + (bz == 0) + (bw == 0);
        h1 += (bx == 1) + (by == 1) + (bz == 1) + (bw == 1);
        h2 += (bx == 2) + (by == 2) + (bz == 2) + (bw == 2);
        h3 += (bx == 3) + (by == 3) + (bz == 3) + (bw == 3);
        h4 += (bx == 4) + (by == 4) + (bz == 4) + (bw == 4);
    }

    __shared__ unsigned int sh[5];
    if (threadIdx.x < 5) sh[threadIdx.x] = 0u;
    __syncthreads();
    // warp-reduce first to cut shared-atomic traffic 32x
    for (int off = 16; off > 0; off >>= 1) {
        h0 += __shfl_down_sync(0xFFFFFFFFu, h0, off);
        h1 += __shfl_down_sync(0xFFFFFFFFu, h1, off);
        h2 += __shfl_down_sync(0xFFFFFFFFu, h2, off);
        h3 += __shfl_down_sync(0xFFFFFFFFu, h3, off);
        h4 += __shfl_down_sync(0xFFFFFFFFu, h4, off);
    }
    if ((threadIdx.x & 31) == 0) {
        atomicAdd(&sh[0], h0);
        atomicAdd(&sh[1], h1);
        atomicAdd(&sh[2], h2);
        atomicAdd(&sh[3], h3);
        atomicAdd(&sh[4], h4);
    }
    __syncthreads();
    if (threadIdx.x < 5) atomicAdd(&g_hist[threadIdx.x], sh[threadIdx.x]);

    // --- last-block finalize ---
    __threadfence();
    __shared__ bool is_last;
    if (threadIdx.x == 0) {
        unsigned int prev = atomicAdd(&g_done, 1u);
        is_last = (prev == gridDim.x - 1);
    }
    __syncthreads();
    if (is_last && threadIdx.x == 0) {
        float* fo = (float*)out;
        unsigned int c0 = g_hist[0], c1 = g_hist[1], c2 = g_hist[2],
                     c3 = g_hist[3], c4 = g_hist[4];
        unsigned long long ones = (unsigned long long)c1
                                + 2ull * c2 + 3ull * c3 + 4ull * c4;
        double zeros = (double)n - (double)ones;
        fo[n]     = (float)(zeros / (double)n);          // sparsity_ratio
        fo[n + 1] = (float)((double)c0 / (double)step);  // coll zero frac
        fo[n + 2] = (float)c0;
        fo[n + 3] = (float)c1;
        fo[n + 4] = (float)c2;
        fo[n + 5] = (float)c3;
        fo[n + 6] = (float)c4;
        // reset scratch for next (graph-replayed) launch
        g_hist[0] = 0u; g_hist[1] = 0u; g_hist[2] = 0u;
        g_hist[3] = 0u; g_hist[4] = 0u;
        g_done = 0u;
    }
}

// ---------------------------------------------------------------------------
// Generic fallback: any T (<= 63), any step. Scalar loads, shared-atomic
// histogram, same last-block finalize.
// ---------------------------------------------------------------------------
__global__ void sparsity_fused_generic(const float* __restrict__ in,
                                       float* __restrict__ out,
                                       long long step, int T, long long n) {
    extern __shared__ unsigned int shh[];
    for (int k = threadIdx.x; k <= T; k += blockDim.x) shh[k] = 0u;
    __syncthreads();

    const long long stride = (long long)gridDim.x * blockDim.x;
    for (long long j = (long long)blockIdx.x * blockDim.x + threadIdx.x;
         j < step; j += stride) {
        float c = 0.f;
        for (int t = 0; t < T; t++) {
            const long long idx = (long long)t * step + j;
            float v = in[idx];
            out[idx] = v;
            c += v;
        }
        atomicAdd(&shh[(int)c], 1u);
    }
    __syncthreads();
    for (int k = threadIdx.x; k <= T; k += blockDim.x)
        atomicAdd(&g_hist[k], shh[k]);

    __threadfence();
    __shared__ bool is_last;
    if (threadIdx.x == 0) {
        unsigned int prev = atomicAdd(&g_done, 1u);
        is_last = (prev == gridDim.x - 1);
    }
    __syncthreads();
    if (is_last && threadIdx.x == 0) {
        unsigned long long ones = 0ull;
        for (int k = 1; k <= T; k++)
            ones += (unsigned long long)k * (unsigned long long)g_hist[k];
        double zeros = (double)n - (double)ones;
        out[n]     = (float)(zeros / (double)n);
        out[n + 1] = (float)((double)g_hist[0] / (double)step);
        for (int k = 0; k <= T; k++) {
            out[n + 2 + k] = (float)g_hist[k];
            g_hist[k] = 0u;
        }
        g_done = 0u;
    }
}

extern "C" void kernel_launch(void* const* d_in, const int* in_sizes, int n_in,
                              void* d_out, int out_size) {
    const float* spikes = (const float*)d_in[0];
    float* out = (float*)d_out;
    const long long n = (long long)in_sizes[0];

    // out_size = n + 1 + 1 + (T+1)  =>  T = out_size - n - 3
    long long T_ll = (long long)out_size - n - 3;
    int T = (T_ll >= 1 && T_ll <= 63 && (n % T_ll) == 0) ? (int)T_ll : 4;
    const long long step = n / T;

    const int threads = 256;
    if (T == 4 && (step % 4) == 0) {
        const long long step4 = step / 4;
        // Single full wave: 5 CTAs/SM (pinned by __launch_bounds__) x 148 SMs.
        int blocks = 148 * 5;
        long long maxb = (step4 + threads - 1) / threads;
        if ((long long)blocks > maxb) blocks = (int)maxb;
        if (blocks < 1) blocks = 1;
        sparsity_fused_t4_v4<<<blocks, threads>>>(
            (const float4*)spikes, (float4*)out, step4, n, step);
    } else {
        int blocks = 148 * 8;
        long long maxb = (step + threads - 1) / threads;
        if ((long long)blocks > maxb) blocks = (int)maxb;
        if (blocks < 1) blocks = 1;
        sparsity_fused_generic<<<blocks, threads, (T + 1) * sizeof(unsigned int)>>>(
            spikes, out, step, T, n);
    }
}